// round 2
// baseline (speedup 1.0000x reference)
#include <cuda_runtime.h>
#include <math.h>

#define N_NODES 100000
#define N_EDGES 1600000
#define IN_DIM  64
#define EMB     128
#define ED      32

// Scratch (static device allocations are allowed)
__device__ float g_agg[2][(size_t)N_NODES * IN_DIM];   // [0]=in (agg@dst), [1]=out (agg@src)
__device__ float g_t[2][(size_t)N_NODES * EMB];        // gelu(h@W1+b1) per direction

// ---------------------------------------------------------------------------
// zero the aggregation buffers
// ---------------------------------------------------------------------------
__global__ void zero_kernel() {
    size_t total = (size_t)2 * N_NODES * IN_DIM / 4;
    float4* p = (float4*)g_agg;
    float4 z = make_float4(0.f, 0.f, 0.f, 0.f);
    for (size_t i = (size_t)blockIdx.x * blockDim.x + threadIdx.x; i < total;
         i += (size_t)gridDim.x * blockDim.x)
        p[i] = z;
}

// ---------------------------------------------------------------------------
// Edge kernel: warp-per-edge, direction-specialized by blockIdx.y.
// msg = relu(x[gather] + ea@We + be), red-add into agg[scatter].
// Thread `lane` owns output dims {2*lane, 2*lane+1}; weights live in registers.
// ---------------------------------------------------------------------------
__global__ __launch_bounds__(256, 2) void edge_kernel(
    const float2* __restrict__ x2,        // x viewed as [N_NODES][32] float2
    const int* __restrict__ ei,           // [2][N_EDGES] int32
    const float* __restrict__ ea,         // [N_EDGES][32]
    const float2* __restrict__ We_in2,    // [32][32] float2 view of [32][64]
    const float2* __restrict__ be_in2,    // [32]
    const float2* __restrict__ We_out2,
    const float2* __restrict__ be_out2)
{
    const int dir  = blockIdx.y;          // 0 = conv_in, 1 = conv_out
    const int lane = threadIdx.x & 31;
    const int w    = threadIdx.x >> 5;

    const float2* We2 = dir ? We_out2 : We_in2;
    const float2  bias = dir ? be_out2[lane] : be_in2[lane];
    // conv_in:  gather src (ei[0]), scatter dst (ei[1])
    // conv_out: gather dst, scatter src
    const int* gidx = dir ? (ei + N_EDGES) : ei;
    const int* sidx = dir ? ei : (ei + N_EDGES);
    float* __restrict__ agg = g_agg[dir];

    float2 wreg[32];
#pragma unroll
    for (int k = 0; k < 32; k++) wreg[k] = We2[k * 32 + lane];

    __shared__ float sEa[8][32];

    const int warpGlobal = blockIdx.x * 8 + w;
    const int nwarps = gridDim.x * 8;

    for (int e = warpGlobal; e < N_EDGES; e += nwarps) {
        int s = gidx[e];
        int d = sidx[e];
        sEa[w][lane] = ea[(size_t)e * 32 + lane];
        __syncwarp();

        float2 acc = x2[(size_t)s * 32 + lane];
        acc.x += bias.x;
        acc.y += bias.y;
#pragma unroll
        for (int k = 0; k < 32; k++) {
            float a = sEa[w][k];
            acc.x = fmaf(a, wreg[k].x, acc.x);
            acc.y = fmaf(a, wreg[k].y, acc.y);
        }
        acc.x = fmaxf(acc.x, 0.f);
        acc.y = fmaxf(acc.y, 0.f);

        float* p = agg + (size_t)d * 64 + 2 * lane;
        asm volatile("red.global.add.v2.f32 [%0], {%1, %2};"
                     :: "l"(p), "f"(acc.x), "f"(acc.y) : "memory");
        __syncwarp();
    }
}

// ---------------------------------------------------------------------------
// GEMM micro-framework: 64(M) x 128(N) block tile, 256 threads, 4x8 microtile,
// K processed in 32-wide chunks. A optionally has an addend and a scale.
// ---------------------------------------------------------------------------
__device__ __forceinline__ void gemm_chunk(
    const float* __restrict__ A, const float* __restrict__ Aadd, int lda4,
    const float* __restrict__ W, int k0, int m0, float scale,
    float (*sAT)[65], float (*sW)[128], float acc[4][8], int tid)
{
    // Stage A chunk: 64 rows x 32 cols, transposed into sAT[k][row]
    const float4* A4  = (const float4*)A;
    const float4* Aa4 = (const float4*)Aadd;
#pragma unroll
    for (int it = 0; it < 2; ++it) {
        int idx = it * 256 + tid;       // 0..511
        int r   = idx >> 3;             // row within tile
        int cq  = idx & 7;              // float4 index within 32-col chunk
        float4 v = make_float4(0.f, 0.f, 0.f, 0.f);
        int gr = m0 + r;
        if (gr < N_NODES) {
            v = A4[(size_t)gr * lda4 + (k0 >> 2) + cq];
            if (Aadd) {
                float4 u = Aa4[(size_t)gr * lda4 + (k0 >> 2) + cq];
                v.x += u.x; v.y += u.y; v.z += u.z; v.w += u.w;
            }
            v.x *= scale; v.y *= scale; v.z *= scale; v.w *= scale;
        }
        sAT[cq * 4 + 0][r] = v.x;
        sAT[cq * 4 + 1][r] = v.y;
        sAT[cq * 4 + 2][r] = v.z;
        sAT[cq * 4 + 3][r] = v.w;
    }
    // Stage W chunk: rows k0..k0+31 of [K][128]
    const float4* W4 = (const float4*)W;
#pragma unroll
    for (int it = 0; it < 4; ++it) {
        int idx = it * 256 + tid;       // 0..1023
        int kr  = idx >> 5;
        int cq  = idx & 31;
        *(float4*)&sW[kr][cq * 4] = W4[(size_t)(k0 + kr) * 32 + cq];
    }
    __syncthreads();

    const int rg = (tid >> 4) * 4;
    const int cg = (tid & 15) * 8;
#pragma unroll
    for (int k = 0; k < 32; k++) {
        float av[4];
        av[0] = sAT[k][rg + 0];
        av[1] = sAT[k][rg + 1];
        av[2] = sAT[k][rg + 2];
        av[3] = sAT[k][rg + 3];
        float bv[8];
        *(float4*)&bv[0] = *(const float4*)&sW[k][cg];
        *(float4*)&bv[4] = *(const float4*)&sW[k][cg + 4];
#pragma unroll
        for (int i = 0; i < 4; i++)
#pragma unroll
            for (int j = 0; j < 8; j++)
                acc[i][j] = fmaf(av[i], bv[j], acc[i][j]);
    }
    __syncthreads();
}

__device__ __forceinline__ float gelu_exact(float v) {
    return 0.5f * v * (1.f + erff(v * 0.70710678118654752f));
}

// ---------------------------------------------------------------------------
// N1: t[dir] = gelu((x + agg[dir]) @ W1 + b1)
// ---------------------------------------------------------------------------
__global__ __launch_bounds__(256) void n1_kernel(
    const float* __restrict__ x,
    const float* __restrict__ W1_in,  const float* __restrict__ b1_in,
    const float* __restrict__ W1_out, const float* __restrict__ b1_out)
{
    const int dir = blockIdx.y;
    const float* W1 = dir ? W1_out : W1_in;
    const float* b1 = dir ? b1_out : b1_in;
    const float* agg = g_agg[dir];
    float* tptr = g_t[dir];

    __shared__ float sAT[32][65];
    __shared__ float sW[32][128];
    float acc[4][8];
#pragma unroll
    for (int i = 0; i < 4; i++)
#pragma unroll
        for (int j = 0; j < 8; j++) acc[i][j] = 0.f;

    const int tid = threadIdx.x;
    const int m0  = blockIdx.x * 64;

    gemm_chunk(x, agg, 16, W1,  0, m0, 1.f, sAT, sW, acc, tid);
    gemm_chunk(x, agg, 16, W1, 32, m0, 1.f, sAT, sW, acc, tid);

    const int rg = (tid >> 4) * 4;
    const int cg = (tid & 15) * 8;
#pragma unroll
    for (int i = 0; i < 4; i++) {
        int gr = m0 + rg + i;
        if (gr < N_NODES) {
            float o[8];
#pragma unroll
            for (int j = 0; j < 8; j++)
                o[j] = gelu_exact(acc[i][j] + b1[cg + j]);
            *(float4*)&tptr[(size_t)gr * EMB + cg]     = *(float4*)&o[0];
            *(float4*)&tptr[(size_t)gr * EMB + cg + 4] = *(float4*)&o[4];
        }
    }
}

// ---------------------------------------------------------------------------
// N2: out = 0.5*(t_out@W2_out + b2_out) + 0.5*(t_in@W2_in + b2_in) + x@Wr + br
// ---------------------------------------------------------------------------
__global__ __launch_bounds__(256) void n2_kernel(
    const float* __restrict__ x,
    const float* __restrict__ W2_in,  const float* __restrict__ b2_in,
    const float* __restrict__ W2_out, const float* __restrict__ b2_out,
    const float* __restrict__ Wr,     const float* __restrict__ br,
    float* __restrict__ out)
{
    __shared__ float sAT[32][65];
    __shared__ float sW[32][128];
    float acc[4][8];
#pragma unroll
    for (int i = 0; i < 4; i++)
#pragma unroll
        for (int j = 0; j < 8; j++) acc[i][j] = 0.f;

    const int tid = threadIdx.x;
    const int m0  = blockIdx.x * 64;

#pragma unroll 1
    for (int k0 = 0; k0 < 128; k0 += 32)
        gemm_chunk(g_t[1], nullptr, 32, W2_out, k0, m0, 0.5f, sAT, sW, acc, tid);
#pragma unroll 1
    for (int k0 = 0; k0 < 128; k0 += 32)
        gemm_chunk(g_t[0], nullptr, 32, W2_in, k0, m0, 0.5f, sAT, sW, acc, tid);
#pragma unroll 1
    for (int k0 = 0; k0 < 64; k0 += 32)
        gemm_chunk(x, nullptr, 16, Wr, k0, m0, 1.f, sAT, sW, acc, tid);

    const int rg = (tid >> 4) * 4;
    const int cg = (tid & 15) * 8;
#pragma unroll
    for (int i = 0; i < 4; i++) {
        int gr = m0 + rg + i;
        if (gr < N_NODES) {
            float o[8];
#pragma unroll
            for (int j = 0; j < 8; j++) {
                float bias = 0.5f * (b2_out[cg + j] + b2_in[cg + j]) + br[cg + j];
                o[j] = acc[i][j] + bias;
            }
            *(float4*)&out[(size_t)gr * EMB + cg]     = *(float4*)&o[0];
            *(float4*)&out[(size_t)gr * EMB + cg + 4] = *(float4*)&o[4];
        }
    }
}

// ---------------------------------------------------------------------------
// launch
// ---------------------------------------------------------------------------
extern "C" void kernel_launch(void* const* d_in, const int* in_sizes, int n_in,
                              void* d_out, int out_size)
{
    const float* x      = (const float*)d_in[0];
    const int*   ei     = (const int*)d_in[1];
    const float* ea     = (const float*)d_in[2];
    const float* We_in  = (const float*)d_in[3];
    const float* be_in  = (const float*)d_in[4];
    const float* W1_in  = (const float*)d_in[5];
    const float* b1_in  = (const float*)d_in[6];
    const float* W2_in  = (const float*)d_in[7];
    const float* b2_in  = (const float*)d_in[8];
    const float* We_out = (const float*)d_in[9];
    const float* be_out = (const float*)d_in[10];
    const float* W1_out = (const float*)d_in[11];
    const float* b1_out = (const float*)d_in[12];
    const float* W2_out = (const float*)d_in[13];
    const float* b2_out = (const float*)d_in[14];
    const float* Wr     = (const float*)d_in[15];
    const float* br     = (const float*)d_in[16];
    float* out = (float*)d_out;

    zero_kernel<<<1024, 256>>>();

    dim3 egrid(2368, 2);
    edge_kernel<<<egrid, 256>>>(
        (const float2*)x, ei, ea,
        (const float2*)We_in,  (const float2*)be_in,
        (const float2*)We_out, (const float2*)be_out);

    dim3 ngrid((N_NODES + 63) / 64, 2);
    n1_kernel<<<ngrid, 256>>>(x, W1_in, b1_in, W1_out, b1_out);

    n2_kernel<<<(N_NODES + 63) / 64, 256>>>(
        x, W2_in, b2_in, W2_out, b2_out, Wr, br, out);
}